// round 13
// baseline (speedup 1.0000x reference)
#include <cuda_runtime.h>
#include <cuda_fp16.h>
#include <math.h>
#include <stdint.h>

#define NB 4
#define NT 4096
#define NC 512
#define NH 64
#define NM (NB*NT)            // 16384 rows

// fp16 operands + split-KV partials
__device__ __half g_wt[192 * NC];                 // [n][k]: n 0-63=k,64-127=q(scaled),128-191=v
__device__ __half g_qh[(size_t)NM * NH], g_kh[(size_t)NM * NH];
__device__ __half g_vt[(size_t)NM * NH];          // [b][h][s]
__device__ float g_po[2][(size_t)NM * NH];
__device__ float g_pl[2][NM];

// ============================ helpers ======================================
__device__ __forceinline__ uint32_t smem_u32(const void* p) {
    uint32_t a;
    asm("{ .reg .u64 t; cvta.to.shared.u64 t, %1; cvt.u32.u64 %0, t; }"
        : "=r"(a) : "l"(p));
    return a;
}

__device__ __forceinline__ void ldsm4(uint32_t& r0, uint32_t& r1,
                                      uint32_t& r2, uint32_t& r3, uint32_t a) {
    asm volatile("ldmatrix.sync.aligned.m8n8.x4.shared.b16 {%0,%1,%2,%3}, [%4];"
        : "=r"(r0), "=r"(r1), "=r"(r2), "=r"(r3) : "r"(a));
}

__device__ __forceinline__ void mma16816(float& c0, float& c1, float& c2, float& c3,
                                         uint32_t a0, uint32_t a1, uint32_t a2, uint32_t a3,
                                         uint32_t b0, uint32_t b1) {
    asm volatile("mma.sync.aligned.m16n8k16.row.col.f32.f16.f16.f32 "
        "{%0,%1,%2,%3}, {%4,%5,%6,%7}, {%8,%9}, {%0,%1,%2,%3};"
        : "+f"(c0), "+f"(c1), "+f"(c2), "+f"(c3)
        : "r"(a0), "r"(a1), "r"(a2), "r"(a3), "r"(b0), "r"(b1));
}

__device__ __forceinline__ uint32_t cvt_h2(float a, float b) {
    __half2 h = __float22half2_rn(make_float2(a, b));
    return *reinterpret_cast<uint32_t*>(&h);
}

#define CP16(dst, src) \
    asm volatile("cp.async.cg.shared.global [%0], [%1], 16;" \
        :: "r"(dst), "l"(src) : "memory")
#define CP_COMMIT() asm volatile("cp.async.commit_group;" ::: "memory")
#define CP_WAIT0()  asm volatile("cp.async.wait_group 0;" ::: "memory")

// ---------------------------------------------------------------------------
// Kernel 0: build W^T fp16 [192][512] from Wk|Wq|Wv (fp32 [512][64]).
// 1/sqrt(C) folded into the q block.  grid (8 k-tiles, 3 matrices).
// ---------------------------------------------------------------------------
__global__ __launch_bounds__(256) void wt_prep_kernel(
    const float* __restrict__ Wk,
    const float* __restrict__ Wq,
    const float* __restrict__ Wv)
{
    __shared__ float t[64][65];
    const int k0  = blockIdx.x * 64;
    const int wsel = blockIdx.y;
    const int tid = threadIdx.x;
    const float* __restrict__ W = (wsel == 0) ? Wk : (wsel == 1) ? Wq : Wv;
    const float scale = (wsel == 1) ? 0.044194173824159216f : 1.0f;

#pragma unroll
    for (int u = 0; u < 4; u++) {
        int f = tid + u * 256;
        int r = f >> 4, c4 = f & 15;
        float4 w4 = *(const float4*)&W[(size_t)(k0 + r) * NH + c4 * 4];
        t[r][c4 * 4 + 0] = w4.x; t[r][c4 * 4 + 1] = w4.y;
        t[r][c4 * 4 + 2] = w4.z; t[r][c4 * 4 + 3] = w4.w;
    }
    __syncthreads();

#pragma unroll
    for (int u = 0; u < 4; u++) {
        int f = tid + u * 256;
        int n = f >> 4, c4 = f & 15;
        uint2 p;
        p.x = cvt_h2(t[c4 * 4 + 0][n] * scale, t[c4 * 4 + 1][n] * scale);
        p.y = cvt_h2(t[c4 * 4 + 2][n] * scale, t[c4 * 4 + 3][n] * scale);
        *(uint2*)&g_wt[(size_t)(wsel * 64 + n) * NC + k0 + c4 * 4] = p;
    }
}

// ---------------------------------------------------------------------------
// Kernel 1: QKV projection on fp16 mma.sync.
// grid (128 M-tiles, 2 N-halves); 256 thr / 8 warps; warp = 16 rows x 96 cols.
// by=1 additionally transposes its v block in smem and writes g_vt [b][h][s]
// coalesced (conv_vt kernel eliminated).
// ---------------------------------------------------------------------------
#define XSTR 40
#define VSTR 136
__global__ __launch_bounds__(256, 2) void proj_kernel(const float* __restrict__ x)
{
    __shared__ char psm[17920];     // xs[128*40] | ws[96*40]; reused as vts[64*136]
    __half* xs = (__half*)psm;
    __half* ws = (__half*)(psm + 10240);

    const int tid  = threadIdx.x;
    const int w    = tid >> 5;
    const int lane = tid & 31;
    const int g    = lane >> 2;
    const int l4   = lane & 3;
    const int m0   = blockIdx.x * 128;
    const int nbase = blockIdx.y * 96;

    const uint32_t xs_b = smem_u32(xs);
    const uint32_t ws_b = smem_u32(ws);

    const int laneA = (lane & 15) * XSTR + ((lane & 16) >> 1);
    const int laneB = ((lane & 7) | ((lane & 16) >> 1)) * XSTR + (lane & 8);

    const int xr = tid >> 1, xh = tid & 1;
    const int wr = tid >> 1, wh = tid & 1;
    const float* xp = x + (size_t)(m0 + xr) * NC + xh * 16;
    const __half* wp = g_wt + (size_t)(nbase + wr) * NC + wh * 16;

    float c[12][4];
#pragma unroll
    for (int j = 0; j < 12; j++)
#pragma unroll
        for (int q = 0; q < 4; q++) c[j][q] = 0.f;

    float4 xr4[4];
    uint4 wr4[2];
#pragma unroll
    for (int q = 0; q < 4; q++) xr4[q] = *(const float4*)(xp + q * 4);
    if (tid < 192) {
        wr4[0] = *(const uint4*)(wp);
        wr4[1] = *(const uint4*)(wp + 8);
    }

    for (int s = 0; s < 16; s++) {
        __syncthreads();
        {
            uint32_t px[8];
#pragma unroll
            for (int q = 0; q < 4; q++) {
                px[q * 2 + 0] = cvt_h2(xr4[q].x, xr4[q].y);
                px[q * 2 + 1] = cvt_h2(xr4[q].z, xr4[q].w);
            }
            uint4* d = (uint4*)&xs[xr * XSTR + xh * 16];
            d[0] = make_uint4(px[0], px[1], px[2], px[3]);
            d[1] = make_uint4(px[4], px[5], px[6], px[7]);
            if (tid < 192) {
                uint4* dw = (uint4*)&ws[wr * XSTR + wh * 16];
                dw[0] = wr4[0];
                dw[1] = wr4[1];
            }
        }
        __syncthreads();

        if (s < 15) {
            const float* xpn = xp + (s + 1) * 32;
#pragma unroll
            for (int q = 0; q < 4; q++) xr4[q] = *(const float4*)(xpn + q * 4);
            if (tid < 192) {
                const __half* wpn = wp + (s + 1) * 32;
                wr4[0] = *(const uint4*)(wpn);
                wr4[1] = *(const uint4*)(wpn + 8);
            }
        }

#pragma unroll
        for (int kc = 0; kc < 2; kc++) {
            uint32_t a0, a1, a2, a3;
            ldsm4(a0, a1, a2, a3,
                  xs_b + (uint32_t)(w * 16 * XSTR + kc * 16 + laneA) * 2);
#pragma unroll
            for (int jp = 0; jp < 6; jp++) {
                uint32_t b0, b1, b2, b3;
                ldsm4(b0, b1, b2, b3,
                      ws_b + (uint32_t)(jp * 16 * XSTR + kc * 16 + laneB) * 2);
                mma16816(c[2*jp][0], c[2*jp][1], c[2*jp][2], c[2*jp][3],
                         a0, a1, a2, a3, b0, b1);
                mma16816(c[2*jp+1][0], c[2*jp+1][1], c[2*jp+1][2], c[2*jp+1][3],
                         a0, a1, a2, a3, b2, b3);
            }
        }
    }

    const int r0 = m0 + w * 16 + g;
    const int r1 = r0 + 8;

    if (nbase == 0) {
        // cols 0..63 = k, 64..95 = q[0..31]
#pragma unroll
        for (int j = 0; j < 12; j++) {
            int col = 8 * j + 2 * l4;
            __half* dst = (col < 64) ? g_kh : g_qh;
            int ci = col & 63;
            *(uint32_t*)&dst[(size_t)r0 * NH + ci] = cvt_h2(c[j][0], c[j][1]);
            *(uint32_t*)&dst[(size_t)r1 * NH + ci] = cvt_h2(c[j][2], c[j][3]);
        }
    } else {
        // cols 96..127 = q[32..63]
#pragma unroll
        for (int j = 0; j < 4; j++) {
            int ci = 32 + 8 * j + 2 * l4;
            *(uint32_t*)&g_qh[(size_t)r0 * NH + ci] = cvt_h2(c[j][0], c[j][1]);
            *(uint32_t*)&g_qh[(size_t)r1 * NH + ci] = cvt_h2(c[j][2], c[j][3]);
        }
        // cols 128..191 = v -> transpose in smem, write g_vt [b][h][s] coalesced
        __syncthreads();                    // xs/ws dead; reuse as vts
        __half* vts = (__half*)psm;         // [64][VSTR]
        const int ls0 = w * 16 + g;         // local row (0..127)
#pragma unroll
        for (int j = 4; j < 12; j++) {
            int hc = 8 * j + 2 * l4 - 32;   // v column (0..62)
            vts[hc * VSTR + ls0]            = __float2half_rn(c[j][0]);
            vts[(hc + 1) * VSTR + ls0]      = __float2half_rn(c[j][1]);
            vts[hc * VSTR + ls0 + 8]        = __float2half_rn(c[j][2]);
            vts[(hc + 1) * VSTR + ls0 + 8]  = __float2half_rn(c[j][3]);
        }
        __syncthreads();
        const int vb = m0 >> 12;            // batch
        const int s0 = m0 & 4095;           // seq offset within batch
        const int h  = tid >> 2;            // 0..63
        const int ss = (tid & 3) * 32;      // s segment
        const uint4* src = (const uint4*)&vts[h * VSTR + ss];
        uint4* dst = (uint4*)&g_vt[((size_t)vb * NH + h) * NT + s0 + ss];
#pragma unroll
        for (int q = 0; q < 4; q++) dst[q] = src[q];
    }
}

// ---------------------------------------------------------------------------
// Kernel 2: FA2-style attention on fp16 mma.sync, split-KV x2, cp.async
// double-buffered.  256 thr / 8 warps; q-tile 128 rows; k-tiles of 64 keys.
// Per-warp fragment code identical to the R11/R12-passing version.
// ---------------------------------------------------------------------------
#define KSTR 72
#define TILE_B (64 * KSTR * 2)      // 9216 B per array
#define BUF_B  (2 * TILE_B)         // 18432 B: {Kh, Vt}
#define SMEM_B (2 * BUF_B)          // 36864 B

__device__ __forceinline__ void fill_tile(uint32_t dstb, int b, int kt, int tid)
{
    const char* khp = (const char*)(g_kh + ((size_t)b * NT + (size_t)kt * 64) * NH);
    const char* vtp = (const char*)(g_vt + (size_t)b * NH * NT + (size_t)kt * 64);
#pragma unroll
    for (int u = 0; u < 2; u++) {
        int f = tid + u * 256;
        int r = f >> 3, c = f & 7;
        uint32_t so = (uint32_t)(r * KSTR) * 2 + c * 16;
        CP16(dstb + so,          khp + (size_t)r * 128 + c * 16);
        CP16(dstb + TILE_B + so, vtp + (size_t)r * (NT * 2) + c * 16);
    }
}

__global__ __launch_bounds__(256, 2) void attn_kernel()
{
    extern __shared__ char smc[];
    const uint32_t smb = smem_u32(smc);

    const int tid  = threadIdx.x;
    const int w    = tid >> 5;                 // 0..7
    const int lane = tid & 31;
    const int g    = lane >> 2;
    const int l4   = lane & 3;
    const int qt   = 31 - (blockIdx.x >> 1);   // LPT over 128-row q-tiles
    const int sp   = blockIdx.x & 1;
    const int b    = blockIdx.y;
    const int lo   = sp * (qt + 1);            // of 2qt+2 k-tiles total
    const int nu   = qt + 1;

    const int rowA = lane & 15;
    const int kofA = (lane & 16) >> 1;
    const int laneA = rowA * KSTR + kofA;
    const int rowB = (lane & 7) | ((lane & 16) >> 1);
    const int kofB = (lane & 8);
    const int laneB = rowB * KSTR + kofB;

    // start tile-0 fill immediately (overlaps Q staging below)
    fill_tile(smb, b, lo, tid);
    CP_COMMIT();

    // ---- stage Q (128 rows fp16) through buf1; capture fragments ----
    uint32_t qh[4][4];
    {
        char* qs = smc + BUF_B;
        const uint32_t qsb = smb + BUF_B;
        const char* qhp = (const char*)(g_qh + ((size_t)b * NT + (size_t)qt * 128) * NH);
#pragma unroll
        for (int u = 0; u < 4; u++) {
            int f = tid + u * 256;             // 0..1023 = 128 rows x 8 chunks
            int r = f >> 3, c = f & 7;
            *(uint4*)(qs + (r * KSTR) * 2 + c * 16) = *(const uint4*)(qhp + r * 128 + c * 16);
        }
        __syncthreads();
#pragma unroll
        for (int kc = 0; kc < 4; kc++)
            ldsm4(qh[kc][0], qh[kc][1], qh[kc][2], qh[kc][3],
                  qsb + (uint32_t)(w * 16 * KSTR + kc * 16 + laneA) * 2);
        __syncthreads();
    }

    float o[8][4];
#pragma unroll
    for (int j = 0; j < 8; j++)
#pragma unroll
        for (int c = 0; c < 4; c++) o[j][c] = 0.f;
    float lth0 = 0.f, lth1 = 0.f;

    const int r0g = qt * 128 + w * 16 + g;
    const int r1g = r0g + 8;

    for (int u = 0; u < nu; u++) {
        const int kt = lo + u;
        const uint32_t bcur = smb + (u & 1) * BUF_B;
        const uint32_t kh_b = bcur;
        const uint32_t vt_b = bcur + TILE_B;

        CP_WAIT0();
        __syncthreads();
        if (u + 1 < nu) {
            fill_tile(smb + ((u + 1) & 1) * BUF_B, b, kt + 1, tid);
            CP_COMMIT();
        }

        // ---- S = Q * K^T ----
        float s[8][4];
#pragma unroll
        for (int j = 0; j < 8; j++)
#pragma unroll
            for (int c = 0; c < 4; c++) s[j][c] = 0.f;

#pragma unroll
        for (int jp = 0; jp < 4; jp++) {
#pragma unroll
            for (int kc = 0; kc < 4; kc++) {
                uint32_t off = (uint32_t)(jp * 16 * KSTR + kc * 16 + laneB) * 2;
                uint32_t b0, b1, b2, b3;
                ldsm4(b0, b1, b2, b3, kh_b + off);
                mma16816(s[2*jp][0], s[2*jp][1], s[2*jp][2], s[2*jp][3],
                         qh[kc][0], qh[kc][1], qh[kc][2], qh[kc][3], b0, b1);
                mma16816(s[2*jp+1][0], s[2*jp+1][1], s[2*jp+1][2], s[2*jp+1][3],
                         qh[kc][0], qh[kc][1], qh[kc][2], qh[kc][3], b2, b3);
            }
        }

        // ---- exp + causal mask; pack rounded P; l from ROUNDED p ----
        uint32_t paH[8][2];
#pragma unroll
        for (int j = 0; j < 8; j++) {
            int cb = kt * 64 + 8 * j + 2 * l4;
            float p00 = (cb     <= r0g) ? __expf(s[j][0]) : 0.f;
            float p01 = (cb + 1 <= r0g) ? __expf(s[j][1]) : 0.f;
            float p10 = (cb     <= r1g) ? __expf(s[j][2]) : 0.f;
            float p11 = (cb + 1 <= r1g) ? __expf(s[j][3]) : 0.f;
            uint32_t h0 = cvt_h2(p00, p01);
            uint32_t h1 = cvt_h2(p10, p11);
            paH[j][0] = h0;
            paH[j][1] = h1;
            __half2 hh0 = *reinterpret_cast<__half2*>(&h0);
            __half2 hh1 = *reinterpret_cast<__half2*>(&h1);
            float2 f0 = __half22float2(hh0);
            float2 f1 = __half22float2(hh1);
            lth0 += f0.x + f0.y;
            lth1 += f1.x + f1.y;
        }

        // ---- O += P * V ----
#pragma unroll
        for (int np = 0; np < 4; np++) {
#pragma unroll
            for (int kc = 0; kc < 4; kc++) {
                uint32_t off = (uint32_t)(np * 16 * KSTR + kc * 16 + laneB) * 2;
                uint32_t b0, b1, b2, b3;
                ldsm4(b0, b1, b2, b3, vt_b + off);
                mma16816(o[2*np][0], o[2*np][1], o[2*np][2], o[2*np][3],
                         paH[2*kc][0], paH[2*kc][1], paH[2*kc+1][0], paH[2*kc+1][1],
                         b0, b1);
                mma16816(o[2*np+1][0], o[2*np+1][1], o[2*np+1][2], o[2*np+1][3],
                         paH[2*kc][0], paH[2*kc][1], paH[2*kc+1][0], paH[2*kc+1][1],
                         b2, b3);
            }
        }
    }

    // ---- reduce l; store unnormalized partials ----
    lth0 += __shfl_xor_sync(0xffffffffu, lth0, 1);
    lth0 += __shfl_xor_sync(0xffffffffu, lth0, 2);
    lth1 += __shfl_xor_sync(0xffffffffu, lth1, 1);
    lth1 += __shfl_xor_sync(0xffffffffu, lth1, 2);

    const size_t row0 = (size_t)b * NT + r0g;
    const size_t row1 = (size_t)b * NT + r1g;
    float* p0 = g_po[sp] + row0 * NH;
    float* p1 = g_po[sp] + row1 * NH;
#pragma unroll
    for (int j = 0; j < 8; j++) {
        int col = 8 * j + 2 * l4;
        *(float2*)&p0[col] = make_float2(o[j][0], o[j][1]);
        *(float2*)&p1[col] = make_float2(o[j][2], o[j][3]);
    }
    if (l4 == 0) {
        g_pl[sp][row0] = lth0;
        g_pl[sp][row1] = lth1;
    }
}

// ---------------------------------------------------------------------------
// Kernel 3: combine the 2 split partials.  out = (o0+o1)/(l0+l1).
// ---------------------------------------------------------------------------
__global__ __launch_bounds__(256) void combine_kernel(float* __restrict__ out)
{
    size_t i = (size_t)blockIdx.x * 256 + threadIdx.x;
    size_t e = i * 4;
    size_t row = e >> 6;
    float inv = 1.0f / (g_pl[0][row] + g_pl[1][row]);
    float4 a = *(const float4*)&g_po[0][e];
    float4 c = *(const float4*)&g_po[1][e];
    float4 o = make_float4((a.x + c.x) * inv, (a.y + c.y) * inv,
                           (a.z + c.z) * inv, (a.w + c.w) * inv);
    *(float4*)&out[e] = o;
}

// ---------------------------------------------------------------------------
extern "C" void kernel_launch(void* const* d_in, const int* in_sizes, int n_in,
                              void* d_out, int out_size)
{
    const float* x  = (const float*)d_in[0];
    const float* Wk = (const float*)d_in[1];
    const float* Wq = (const float*)d_in[2];
    const float* Wv = (const float*)d_in[3];
    float* out = (float*)d_out;

    cudaFuncSetAttribute(attn_kernel,
                         cudaFuncAttributeMaxDynamicSharedMemorySize, SMEM_B);

    wt_prep_kernel<<<dim3(8, 3), 256>>>(Wk, Wq, Wv);
    proj_kernel<<<dim3(128, 2), 256>>>(x);
    attn_kernel<<<dim3(64, NB), 256, SMEM_B>>>();
    combine_kernel<<<1024, 256>>>(out);
}

// round 14
// speedup vs baseline: 1.0795x; 1.0795x over previous
#include <cuda_runtime.h>
#include <cuda_fp16.h>
#include <math.h>
#include <stdint.h>

#define NB 4
#define NT 4096
#define NC 512
#define NH 64
#define NM (NB*NT)            // 16384 rows

// fp16 operands + split-KV partials
__device__ __half g_wt[192 * NC];                 // [n][k]: n 0-63=k,64-127=q(scaled),128-191=v
__device__ __half g_qh[(size_t)NM * NH], g_kh[(size_t)NM * NH];
__device__ __half g_vt[(size_t)NM * NH];          // [b][h][s]
__device__ float g_po[2][(size_t)NM * NH];
__device__ float g_pl[2][NM];

// ============================ helpers ======================================
__device__ __forceinline__ uint32_t smem_u32(const void* p) {
    uint32_t a;
    asm("{ .reg .u64 t; cvta.to.shared.u64 t, %1; cvt.u32.u64 %0, t; }"
        : "=r"(a) : "l"(p));
    return a;
}

__device__ __forceinline__ void ldsm4(uint32_t& r0, uint32_t& r1,
                                      uint32_t& r2, uint32_t& r3, uint32_t a) {
    asm volatile("ldmatrix.sync.aligned.m8n8.x4.shared.b16 {%0,%1,%2,%3}, [%4];"
        : "=r"(r0), "=r"(r1), "=r"(r2), "=r"(r3) : "r"(a));
}

__device__ __forceinline__ void mma16816(float& c0, float& c1, float& c2, float& c3,
                                         uint32_t a0, uint32_t a1, uint32_t a2, uint32_t a3,
                                         uint32_t b0, uint32_t b1) {
    asm volatile("mma.sync.aligned.m16n8k16.row.col.f32.f16.f16.f32 "
        "{%0,%1,%2,%3}, {%4,%5,%6,%7}, {%8,%9}, {%0,%1,%2,%3};"
        : "+f"(c0), "+f"(c1), "+f"(c2), "+f"(c3)
        : "r"(a0), "r"(a1), "r"(a2), "r"(a3), "r"(b0), "r"(b1));
}

__device__ __forceinline__ uint32_t cvt_h2(float a, float b) {
    __half2 h = __float22half2_rn(make_float2(a, b));
    return *reinterpret_cast<uint32_t*>(&h);
}

#define CP16(dst, src) \
    asm volatile("cp.async.cg.shared.global [%0], [%1], 16;" \
        :: "r"(dst), "l"(src) : "memory")
#define CP_COMMIT() asm volatile("cp.async.commit_group;" ::: "memory")
#define CP_WAIT0()  asm volatile("cp.async.wait_group 0;" ::: "memory")

// ---------------------------------------------------------------------------
// Kernel 0: build W^T fp16 [192][512] from Wk|Wq|Wv (fp32 [512][64]).
// 1/sqrt(C) folded into the q block.  grid (8 k-tiles, 3 matrices).
// ---------------------------------------------------------------------------
__global__ __launch_bounds__(256) void wt_prep_kernel(
    const float* __restrict__ Wk,
    const float* __restrict__ Wq,
    const float* __restrict__ Wv)
{
    __shared__ float t[64][65];
    const int k0  = blockIdx.x * 64;
    const int wsel = blockIdx.y;
    const int tid = threadIdx.x;
    const float* __restrict__ W = (wsel == 0) ? Wk : (wsel == 1) ? Wq : Wv;
    const float scale = (wsel == 1) ? 0.044194173824159216f : 1.0f;

#pragma unroll
    for (int u = 0; u < 4; u++) {
        int f = tid + u * 256;
        int r = f >> 4, c4 = f & 15;
        float4 w4 = *(const float4*)&W[(size_t)(k0 + r) * NH + c4 * 4];
        t[r][c4 * 4 + 0] = w4.x; t[r][c4 * 4 + 1] = w4.y;
        t[r][c4 * 4 + 2] = w4.z; t[r][c4 * 4 + 3] = w4.w;
    }
    __syncthreads();

#pragma unroll
    for (int u = 0; u < 4; u++) {
        int f = tid + u * 256;
        int n = f >> 4, c4 = f & 15;
        uint2 p;
        p.x = cvt_h2(t[c4 * 4 + 0][n] * scale, t[c4 * 4 + 1][n] * scale);
        p.y = cvt_h2(t[c4 * 4 + 2][n] * scale, t[c4 * 4 + 3][n] * scale);
        *(uint2*)&g_wt[(size_t)(wsel * 64 + n) * NC + k0 + c4 * 4] = p;
    }
}

// ---------------------------------------------------------------------------
// Kernel 1: QKV projection on fp16 mma.sync (R13-passing version, kept).
// by=1 transposes its v block in smem and writes g_vt [b][h][s] coalesced.
// ---------------------------------------------------------------------------
#define XSTR 40
#define VSTR 136
__global__ __launch_bounds__(256, 2) void proj_kernel(const float* __restrict__ x)
{
    __shared__ char psm[17920];     // xs[128*40] | ws[96*40]; reused as vts[64*136]
    __half* xs = (__half*)psm;
    __half* ws = (__half*)(psm + 10240);

    const int tid  = threadIdx.x;
    const int w    = tid >> 5;
    const int lane = tid & 31;
    const int g    = lane >> 2;
    const int l4   = lane & 3;
    const int m0   = blockIdx.x * 128;
    const int nbase = blockIdx.y * 96;

    const uint32_t xs_b = smem_u32(xs);
    const uint32_t ws_b = smem_u32(ws);

    const int laneA = (lane & 15) * XSTR + ((lane & 16) >> 1);
    const int laneB = ((lane & 7) | ((lane & 16) >> 1)) * XSTR + (lane & 8);

    const int xr = tid >> 1, xh = tid & 1;
    const int wr = tid >> 1, wh = tid & 1;
    const float* xp = x + (size_t)(m0 + xr) * NC + xh * 16;
    const __half* wp = g_wt + (size_t)(nbase + wr) * NC + wh * 16;

    float c[12][4];
#pragma unroll
    for (int j = 0; j < 12; j++)
#pragma unroll
        for (int q = 0; q < 4; q++) c[j][q] = 0.f;

    float4 xr4[4];
    uint4 wr4[2];
#pragma unroll
    for (int q = 0; q < 4; q++) xr4[q] = *(const float4*)(xp + q * 4);
    if (tid < 192) {
        wr4[0] = *(const uint4*)(wp);
        wr4[1] = *(const uint4*)(wp + 8);
    }

    for (int s = 0; s < 16; s++) {
        __syncthreads();
        {
            uint32_t px[8];
#pragma unroll
            for (int q = 0; q < 4; q++) {
                px[q * 2 + 0] = cvt_h2(xr4[q].x, xr4[q].y);
                px[q * 2 + 1] = cvt_h2(xr4[q].z, xr4[q].w);
            }
            uint4* d = (uint4*)&xs[xr * XSTR + xh * 16];
            d[0] = make_uint4(px[0], px[1], px[2], px[3]);
            d[1] = make_uint4(px[4], px[5], px[6], px[7]);
            if (tid < 192) {
                uint4* dw = (uint4*)&ws[wr * XSTR + wh * 16];
                dw[0] = wr4[0];
                dw[1] = wr4[1];
            }
        }
        __syncthreads();

        if (s < 15) {
            const float* xpn = xp + (s + 1) * 32;
#pragma unroll
            for (int q = 0; q < 4; q++) xr4[q] = *(const float4*)(xpn + q * 4);
            if (tid < 192) {
                const __half* wpn = wp + (s + 1) * 32;
                wr4[0] = *(const uint4*)(wpn);
                wr4[1] = *(const uint4*)(wpn + 8);
            }
        }

#pragma unroll
        for (int kc = 0; kc < 2; kc++) {
            uint32_t a0, a1, a2, a3;
            ldsm4(a0, a1, a2, a3,
                  xs_b + (uint32_t)(w * 16 * XSTR + kc * 16 + laneA) * 2);
#pragma unroll
            for (int jp = 0; jp < 6; jp++) {
                uint32_t b0, b1, b2, b3;
                ldsm4(b0, b1, b2, b3,
                      ws_b + (uint32_t)(jp * 16 * XSTR + kc * 16 + laneB) * 2);
                mma16816(c[2*jp][0], c[2*jp][1], c[2*jp][2], c[2*jp][3],
                         a0, a1, a2, a3, b0, b1);
                mma16816(c[2*jp+1][0], c[2*jp+1][1], c[2*jp+1][2], c[2*jp+1][3],
                         a0, a1, a2, a3, b2, b3);
            }
        }
    }

    const int r0 = m0 + w * 16 + g;
    const int r1 = r0 + 8;

    if (nbase == 0) {
        // cols 0..63 = k, 64..95 = q[0..31]
#pragma unroll
        for (int j = 0; j < 12; j++) {
            int col = 8 * j + 2 * l4;
            __half* dst = (col < 64) ? g_kh : g_qh;
            int ci = col & 63;
            *(uint32_t*)&dst[(size_t)r0 * NH + ci] = cvt_h2(c[j][0], c[j][1]);
            *(uint32_t*)&dst[(size_t)r1 * NH + ci] = cvt_h2(c[j][2], c[j][3]);
        }
    } else {
        // cols 96..127 = q[32..63]
#pragma unroll
        for (int j = 0; j < 4; j++) {
            int ci = 32 + 8 * j + 2 * l4;
            *(uint32_t*)&g_qh[(size_t)r0 * NH + ci] = cvt_h2(c[j][0], c[j][1]);
            *(uint32_t*)&g_qh[(size_t)r1 * NH + ci] = cvt_h2(c[j][2], c[j][3]);
        }
        // cols 128..191 = v -> transpose in smem, write g_vt [b][h][s] coalesced
        __syncthreads();                    // xs/ws dead; reuse as vts
        __half* vts = (__half*)psm;         // [64][VSTR]
        const int ls0 = w * 16 + g;         // local row (0..127)
#pragma unroll
        for (int j = 4; j < 12; j++) {
            int hc = 8 * j + 2 * l4 - 32;   // v column (0..62)
            vts[hc * VSTR + ls0]            = __float2half_rn(c[j][0]);
            vts[(hc + 1) * VSTR + ls0]      = __float2half_rn(c[j][1]);
            vts[hc * VSTR + ls0 + 8]        = __float2half_rn(c[j][2]);
            vts[(hc + 1) * VSTR + ls0 + 8]  = __float2half_rn(c[j][3]);
        }
        __syncthreads();
        const int vb = m0 >> 12;            // batch
        const int s0 = m0 & 4095;           // seq offset within batch
        const int h  = tid >> 2;            // 0..63
        const int ss = (tid & 3) * 32;      // s segment
        const uint4* src = (const uint4*)&vts[h * VSTR + ss];
        uint4* dst = (uint4*)&g_vt[((size_t)vb * NH + h) * NT + s0 + ss];
#pragma unroll
        for (int q = 0; q < 4; q++) dst[q] = src[q];
    }
}

// ---------------------------------------------------------------------------
// Kernel 2: FA2-style attention on fp16 mma.sync — EXACT R12-passing shape:
// 128 thr / 4 warps, 64-row q-tiles, split-KV x2, 512 LPT CTAs, 3 CTAs/SM.
// Tile-0 fill issued before Q staging (overlap micro-fix from R13).
// ---------------------------------------------------------------------------
#define KSTR 72
#define TILE_B (64 * KSTR * 2)      // 9216 B per array
#define BUF_B  (2 * TILE_B)         // 18432 B: {Kh, Vt}
#define SMEM_B (2 * BUF_B)          // 36864 B

__device__ __forceinline__ void fill_tile(uint32_t dstb, int b, int kt, int tid)
{
    const char* khp = (const char*)(g_kh + ((size_t)b * NT + (size_t)kt * 64) * NH);
    const char* vtp = (const char*)(g_vt + (size_t)b * NH * NT + (size_t)kt * 64);
#pragma unroll
    for (int u = 0; u < 4; u++) {
        int f = tid + u * 128;
        int r = f >> 3, c = f & 7;
        uint32_t so = (uint32_t)(r * KSTR) * 2 + c * 16;
        CP16(dstb + so,          khp + (size_t)r * 128 + c * 16);
        CP16(dstb + TILE_B + so, vtp + (size_t)r * (NT * 2) + c * 16);
    }
}

__global__ __launch_bounds__(128, 3) void attn_kernel()
{
    extern __shared__ char smc[];
    const uint32_t smb = smem_u32(smc);

    const int tid  = threadIdx.x;
    const int w    = tid >> 5;
    const int lane = tid & 31;
    const int g    = lane >> 2;
    const int l4   = lane & 3;
    const int qt   = 63 - (blockIdx.x >> 1);   // LPT
    const int sp   = blockIdx.x & 1;
    const int b    = blockIdx.y;
    const int lo   = sp * (qt + 1) / 2;
    const int hi   = (sp + 1) * (qt + 1) / 2;
    const int nu   = hi - lo;

    const int rowA = lane & 15;
    const int kofA = (lane & 16) >> 1;
    const int laneA = rowA * KSTR + kofA;
    const int rowB = (lane & 7) | ((lane & 16) >> 1);
    const int kofB = (lane & 8);
    const int laneB = rowB * KSTR + kofB;

    // start tile-0 fill immediately (overlaps Q staging below)
    if (nu > 0) { fill_tile(smb, b, lo, tid); CP_COMMIT(); }

    // ---- stage Q (fp16) through buf1's Kh area; capture fragments ----
    uint32_t qh[4][4];
    {
        char* qs = smc + BUF_B;
        const uint32_t qsb = smb + BUF_B;
        const char* qhp = (const char*)(g_qh + ((size_t)b * NT + (size_t)qt * 64) * NH);
#pragma unroll
        for (int u = 0; u < 4; u++) {
            int f = tid + u * 128;
            int r = f >> 3, c = f & 7;
            *(uint4*)(qs + (r * KSTR) * 2 + c * 16) = *(const uint4*)(qhp + r * 128 + c * 16);
        }
        __syncthreads();
#pragma unroll
        for (int kc = 0; kc < 4; kc++)
            ldsm4(qh[kc][0], qh[kc][1], qh[kc][2], qh[kc][3],
                  qsb + (uint32_t)(w * 16 * KSTR + kc * 16 + laneA) * 2);
        __syncthreads();
    }

    float o[8][4];
#pragma unroll
    for (int j = 0; j < 8; j++)
#pragma unroll
        for (int c = 0; c < 4; c++) o[j][c] = 0.f;
    float lth0 = 0.f, lth1 = 0.f;

    const int r0g = qt * 64 + w * 16 + g;
    const int r1g = r0g + 8;

    for (int u = 0; u < nu; u++) {
        const int kt = lo + u;
        const uint32_t bcur = smb + (u & 1) * BUF_B;
        const uint32_t kh_b = bcur;
        const uint32_t vt_b = bcur + TILE_B;

        CP_WAIT0();
        __syncthreads();
        if (u + 1 < nu) {
            fill_tile(smb + ((u + 1) & 1) * BUF_B, b, kt + 1, tid);
            CP_COMMIT();
        }

        // ---- S = Q * K^T ----
        float s[8][4];
#pragma unroll
        for (int j = 0; j < 8; j++)
#pragma unroll
            for (int c = 0; c < 4; c++) s[j][c] = 0.f;

#pragma unroll
        for (int jp = 0; jp < 4; jp++) {
#pragma unroll
            for (int kc = 0; kc < 4; kc++) {
                uint32_t off = (uint32_t)(jp * 16 * KSTR + kc * 16 + laneB) * 2;
                uint32_t b0, b1, b2, b3;
                ldsm4(b0, b1, b2, b3, kh_b + off);
                mma16816(s[2*jp][0], s[2*jp][1], s[2*jp][2], s[2*jp][3],
                         qh[kc][0], qh[kc][1], qh[kc][2], qh[kc][3], b0, b1);
                mma16816(s[2*jp+1][0], s[2*jp+1][1], s[2*jp+1][2], s[2*jp+1][3],
                         qh[kc][0], qh[kc][1], qh[kc][2], qh[kc][3], b2, b3);
            }
        }

        // ---- exp + causal mask; pack rounded P; l from ROUNDED p ----
        uint32_t paH[8][2];
#pragma unroll
        for (int j = 0; j < 8; j++) {
            int cb = kt * 64 + 8 * j + 2 * l4;
            float p00 = (cb     <= r0g) ? __expf(s[j][0]) : 0.f;
            float p01 = (cb + 1 <= r0g) ? __expf(s[j][1]) : 0.f;
            float p10 = (cb     <= r1g) ? __expf(s[j][2]) : 0.f;
            float p11 = (cb + 1 <= r1g) ? __expf(s[j][3]) : 0.f;
            uint32_t h0 = cvt_h2(p00, p01);
            uint32_t h1 = cvt_h2(p10, p11);
            paH[j][0] = h0;
            paH[j][1] = h1;
            __half2 hh0 = *reinterpret_cast<__half2*>(&h0);
            __half2 hh1 = *reinterpret_cast<__half2*>(&h1);
            float2 f0 = __half22float2(hh0);
            float2 f1 = __half22float2(hh1);
            lth0 += f0.x + f0.y;
            lth1 += f1.x + f1.y;
        }

        // ---- O += P * V ----
#pragma unroll
        for (int np = 0; np < 4; np++) {
#pragma unroll
            for (int kc = 0; kc < 4; kc++) {
                uint32_t off = (uint32_t)(np * 16 * KSTR + kc * 16 + laneB) * 2;
                uint32_t b0, b1, b2, b3;
                ldsm4(b0, b1, b2, b3, vt_b + off);
                mma16816(o[2*np][0], o[2*np][1], o[2*np][2], o[2*np][3],
                         paH[2*kc][0], paH[2*kc][1], paH[2*kc+1][0], paH[2*kc+1][1],
                         b0, b1);
                mma16816(o[2*np+1][0], o[2*np+1][1], o[2*np+1][2], o[2*np+1][3],
                         paH[2*kc][0], paH[2*kc][1], paH[2*kc+1][0], paH[2*kc+1][1],
                         b2, b3);
            }
        }
    }

    // ---- reduce l; store unnormalized partials ----
    lth0 += __shfl_xor_sync(0xffffffffu, lth0, 1);
    lth0 += __shfl_xor_sync(0xffffffffu, lth0, 2);
    lth1 += __shfl_xor_sync(0xffffffffu, lth1, 1);
    lth1 += __shfl_xor_sync(0xffffffffu, lth1, 2);

    const size_t row0 = (size_t)b * NT + r0g;
    const size_t row1 = (size_t)b * NT + r1g;
    float* p0 = g_po[sp] + row0 * NH;
    float* p1 = g_po[sp] + row1 * NH;
#pragma unroll
    for (int j = 0; j < 8; j++) {
        int col = 8 * j + 2 * l4;
        *(float2*)&p0[col] = make_float2(o[j][0], o[j][1]);
        *(float2*)&p1[col] = make_float2(o[j][2], o[j][3]);
    }
    if (l4 == 0) {
        g_pl[sp][row0] = lth0;
        g_pl[sp][row1] = lth1;
    }
}

// ---------------------------------------------------------------------------
// Kernel 3: combine the 2 split partials.  out = (o0+o1)/(l0+l1).
// ---------------------------------------------------------------------------
__global__ __launch_bounds__(256) void combine_kernel(float* __restrict__ out)
{
    size_t i = (size_t)blockIdx.x * 256 + threadIdx.x;
    size_t e = i * 4;
    size_t row = e >> 6;
    float inv = 1.0f / (g_pl[0][row] + g_pl[1][row]);
    float4 a = *(const float4*)&g_po[0][e];
    float4 c = *(const float4*)&g_po[1][e];
    float4 o = make_float4((a.x + c.x) * inv, (a.y + c.y) * inv,
                           (a.z + c.z) * inv, (a.w + c.w) * inv);
    *(float4*)&out[e] = o;
}

// ---------------------------------------------------------------------------
extern "C" void kernel_launch(void* const* d_in, const int* in_sizes, int n_in,
                              void* d_out, int out_size)
{
    const float* x  = (const float*)d_in[0];
    const float* Wk = (const float*)d_in[1];
    const float* Wq = (const float*)d_in[2];
    const float* Wv = (const float*)d_in[3];
    float* out = (float*)d_out;

    cudaFuncSetAttribute(attn_kernel,
                         cudaFuncAttributeMaxDynamicSharedMemorySize, SMEM_B);

    wt_prep_kernel<<<dim3(8, 3), 256>>>(Wk, Wq, Wv);
    proj_kernel<<<dim3(128, 2), 256>>>(x);
    attn_kernel<<<dim3(128, NB), 128, SMEM_B>>>();
    combine_kernel<<<1024, 256>>>(out);
}

// round 15
// speedup vs baseline: 1.1142x; 1.0322x over previous
#include <cuda_runtime.h>
#include <cuda_fp16.h>
#include <math.h>
#include <stdint.h>

#define NB 4
#define NT 4096
#define NC 512
#define NH 64
#define NM (NB*NT)            // 16384 rows

// fp16 operands + split-KV partials
__device__ __half g_wt[192 * NC];                 // [n][k]: n 0-63=k,64-127=q(scaled),128-191=v
__device__ __half g_qh[(size_t)NM * NH], g_kh[(size_t)NM * NH];
__device__ __half g_vt[(size_t)NM * NH];          // [b][h][s]
__device__ float g_po[2][(size_t)NM * NH];
__device__ float g_pl[2][NM];

// ============================ helpers ======================================
__device__ __forceinline__ uint32_t smem_u32(const void* p) {
    uint32_t a;
    asm("{ .reg .u64 t; cvta.to.shared.u64 t, %1; cvt.u32.u64 %0, t; }"
        : "=r"(a) : "l"(p));
    return a;
}

__device__ __forceinline__ void ldsm4(uint32_t& r0, uint32_t& r1,
                                      uint32_t& r2, uint32_t& r3, uint32_t a) {
    asm volatile("ldmatrix.sync.aligned.m8n8.x4.shared.b16 {%0,%1,%2,%3}, [%4];"
        : "=r"(r0), "=r"(r1), "=r"(r2), "=r"(r3) : "r"(a));
}

__device__ __forceinline__ void mma16816(float& c0, float& c1, float& c2, float& c3,
                                         uint32_t a0, uint32_t a1, uint32_t a2, uint32_t a3,
                                         uint32_t b0, uint32_t b1) {
    asm volatile("mma.sync.aligned.m16n8k16.row.col.f32.f16.f16.f32 "
        "{%0,%1,%2,%3}, {%4,%5,%6,%7}, {%8,%9}, {%0,%1,%2,%3};"
        : "+f"(c0), "+f"(c1), "+f"(c2), "+f"(c3)
        : "r"(a0), "r"(a1), "r"(a2), "r"(a3), "r"(b0), "r"(b1));
}

__device__ __forceinline__ uint32_t cvt_h2(float a, float b) {
    __half2 h = __float22half2_rn(make_float2(a, b));
    return *reinterpret_cast<uint32_t*>(&h);
}

#define CP16(dst, src) \
    asm volatile("cp.async.cg.shared.global [%0], [%1], 16;" \
        :: "r"(dst), "l"(src) : "memory")
#define CP_COMMIT() asm volatile("cp.async.commit_group;" ::: "memory")
#define CP_WAIT0()  asm volatile("cp.async.wait_group 0;" ::: "memory")

// ---------------------------------------------------------------------------
// Kernel 0: build W^T fp16 [192][512] from Wk|Wq|Wv (fp32 [512][64]).
// ---------------------------------------------------------------------------
__global__ __launch_bounds__(256) void wt_prep_kernel(
    const float* __restrict__ Wk,
    const float* __restrict__ Wq,
    const float* __restrict__ Wv)
{
    __shared__ float t[64][65];
    const int k0  = blockIdx.x * 64;
    const int wsel = blockIdx.y;
    const int tid = threadIdx.x;
    const float* __restrict__ W = (wsel == 0) ? Wk : (wsel == 1) ? Wq : Wv;
    const float scale = (wsel == 1) ? 0.044194173824159216f : 1.0f;

#pragma unroll
    for (int u = 0; u < 4; u++) {
        int f = tid + u * 256;
        int r = f >> 4, c4 = f & 15;
        float4 w4 = *(const float4*)&W[(size_t)(k0 + r) * NH + c4 * 4];
        t[r][c4 * 4 + 0] = w4.x; t[r][c4 * 4 + 1] = w4.y;
        t[r][c4 * 4 + 2] = w4.z; t[r][c4 * 4 + 3] = w4.w;
    }
    __syncthreads();

#pragma unroll
    for (int u = 0; u < 4; u++) {
        int f = tid + u * 256;
        int n = f >> 4, c4 = f & 15;
        uint2 p;
        p.x = cvt_h2(t[c4 * 4 + 0][n] * scale, t[c4 * 4 + 1][n] * scale);
        p.y = cvt_h2(t[c4 * 4 + 2][n] * scale, t[c4 * 4 + 3][n] * scale);
        *(uint2*)&g_wt[(size_t)(wsel * 64 + n) * NC + k0 + c4 * 4] = p;
    }
}

// ---------------------------------------------------------------------------
// Kernel 1: QKV projection on fp16 mma.sync (R14-passing version, unchanged).
// ---------------------------------------------------------------------------
#define XSTR 40
#define VSTR 136
__global__ __launch_bounds__(256, 2) void proj_kernel(const float* __restrict__ x)
{
    __shared__ char psm[17920];     // xs[128*40] | ws[96*40]; reused as vts[64*136]
    __half* xs = (__half*)psm;
    __half* ws = (__half*)(psm + 10240);

    const int tid  = threadIdx.x;
    const int w    = tid >> 5;
    const int lane = tid & 31;
    const int g    = lane >> 2;
    const int l4   = lane & 3;
    const int m0   = blockIdx.x * 128;
    const int nbase = blockIdx.y * 96;

    const uint32_t xs_b = smem_u32(xs);
    const uint32_t ws_b = smem_u32(ws);

    const int laneA = (lane & 15) * XSTR + ((lane & 16) >> 1);
    const int laneB = ((lane & 7) | ((lane & 16) >> 1)) * XSTR + (lane & 8);

    const int xr = tid >> 1, xh = tid & 1;
    const int wr = tid >> 1, wh = tid & 1;
    const float* xp = x + (size_t)(m0 + xr) * NC + xh * 16;
    const __half* wp = g_wt + (size_t)(nbase + wr) * NC + wh * 16;

    float c[12][4];
#pragma unroll
    for (int j = 0; j < 12; j++)
#pragma unroll
        for (int q = 0; q < 4; q++) c[j][q] = 0.f;

    float4 xr4[4];
    uint4 wr4[2];
#pragma unroll
    for (int q = 0; q < 4; q++) xr4[q] = *(const float4*)(xp + q * 4);
    if (tid < 192) {
        wr4[0] = *(const uint4*)(wp);
        wr4[1] = *(const uint4*)(wp + 8);
    }

    for (int s = 0; s < 16; s++) {
        __syncthreads();
        {
            uint32_t px[8];
#pragma unroll
            for (int q = 0; q < 4; q++) {
                px[q * 2 + 0] = cvt_h2(xr4[q].x, xr4[q].y);
                px[q * 2 + 1] = cvt_h2(xr4[q].z, xr4[q].w);
            }
            uint4* d = (uint4*)&xs[xr * XSTR + xh * 16];
            d[0] = make_uint4(px[0], px[1], px[2], px[3]);
            d[1] = make_uint4(px[4], px[5], px[6], px[7]);
            if (tid < 192) {
                uint4* dw = (uint4*)&ws[wr * XSTR + wh * 16];
                dw[0] = wr4[0];
                dw[1] = wr4[1];
            }
        }
        __syncthreads();

        if (s < 15) {
            const float* xpn = xp + (s + 1) * 32;
#pragma unroll
            for (int q = 0; q < 4; q++) xr4[q] = *(const float4*)(xpn + q * 4);
            if (tid < 192) {
                const __half* wpn = wp + (s + 1) * 32;
                wr4[0] = *(const uint4*)(wpn);
                wr4[1] = *(const uint4*)(wpn + 8);
            }
        }

#pragma unroll
        for (int kc = 0; kc < 2; kc++) {
            uint32_t a0, a1, a2, a3;
            ldsm4(a0, a1, a2, a3,
                  xs_b + (uint32_t)(w * 16 * XSTR + kc * 16 + laneA) * 2);
#pragma unroll
            for (int jp = 0; jp < 6; jp++) {
                uint32_t b0, b1, b2, b3;
                ldsm4(b0, b1, b2, b3,
                      ws_b + (uint32_t)(jp * 16 * XSTR + kc * 16 + laneB) * 2);
                mma16816(c[2*jp][0], c[2*jp][1], c[2*jp][2], c[2*jp][3],
                         a0, a1, a2, a3, b0, b1);
                mma16816(c[2*jp+1][0], c[2*jp+1][1], c[2*jp+1][2], c[2*jp+1][3],
                         a0, a1, a2, a3, b2, b3);
            }
        }
    }

    const int r0 = m0 + w * 16 + g;
    const int r1 = r0 + 8;

    if (nbase == 0) {
#pragma unroll
        for (int j = 0; j < 12; j++) {
            int col = 8 * j + 2 * l4;
            __half* dst = (col < 64) ? g_kh : g_qh;
            int ci = col & 63;
            *(uint32_t*)&dst[(size_t)r0 * NH + ci] = cvt_h2(c[j][0], c[j][1]);
            *(uint32_t*)&dst[(size_t)r1 * NH + ci] = cvt_h2(c[j][2], c[j][3]);
        }
    } else {
#pragma unroll
        for (int j = 0; j < 4; j++) {
            int ci = 32 + 8 * j + 2 * l4;
            *(uint32_t*)&g_qh[(size_t)r0 * NH + ci] = cvt_h2(c[j][0], c[j][1]);
            *(uint32_t*)&g_qh[(size_t)r1 * NH + ci] = cvt_h2(c[j][2], c[j][3]);
        }
        __syncthreads();
        __half* vts = (__half*)psm;         // [64][VSTR]
        const int ls0 = w * 16 + g;
#pragma unroll
        for (int j = 4; j < 12; j++) {
            int hc = 8 * j + 2 * l4 - 32;
            vts[hc * VSTR + ls0]            = __float2half_rn(c[j][0]);
            vts[(hc + 1) * VSTR + ls0]      = __float2half_rn(c[j][1]);
            vts[hc * VSTR + ls0 + 8]        = __float2half_rn(c[j][2]);
            vts[(hc + 1) * VSTR + ls0 + 8]  = __float2half_rn(c[j][3]);
        }
        __syncthreads();
        const int vb = m0 >> 12;
        const int s0 = m0 & 4095;
        const int h  = tid >> 2;
        const int ss = (tid & 3) * 32;
        const uint4* src = (const uint4*)&vts[h * VSTR + ss];
        uint4* dst = (uint4*)&g_vt[((size_t)vb * NH + h) * NT + s0 + ss];
#pragma unroll
        for (int q = 0; q < 4; q++) dst[q] = src[q];
    }
}

// ---------------------------------------------------------------------------
// Kernel 2: FA2-style attention, chunk-interleaved S->exp->PV per 16-key
// chunk (same arithmetic, shorter dependency chains, fewer live regs).
// 128 thr / 4 warps, 64-row q-tiles, split-KV x2, 512 LPT CTAs, 4 CTAs/SM.
// ---------------------------------------------------------------------------
#define KSTR 72
#define TILE_B (64 * KSTR * 2)      // 9216 B per array
#define BUF_B  (2 * TILE_B)         // 18432 B: {Kh, Vt}
#define SMEM_B (2 * BUF_B)          // 36864 B

__device__ __forceinline__ void fill_tile(uint32_t dstb, int b, int kt, int tid)
{
    const char* khp = (const char*)(g_kh + ((size_t)b * NT + (size_t)kt * 64) * NH);
    const char* vtp = (const char*)(g_vt + (size_t)b * NH * NT + (size_t)kt * 64);
#pragma unroll
    for (int u = 0; u < 4; u++) {
        int f = tid + u * 128;
        int r = f >> 3, c = f & 7;
        uint32_t so = (uint32_t)(r * KSTR) * 2 + c * 16;
        CP16(dstb + so,          khp + (size_t)r * 128 + c * 16);
        CP16(dstb + TILE_B + so, vtp + (size_t)r * (NT * 2) + c * 16);
    }
}

__global__ __launch_bounds__(128, 4) void attn_kernel()
{
    extern __shared__ char smc[];
    const uint32_t smb = smem_u32(smc);

    const int tid  = threadIdx.x;
    const int w    = tid >> 5;
    const int lane = tid & 31;
    const int g    = lane >> 2;
    const int l4   = lane & 3;
    const int qt   = 63 - (blockIdx.x >> 1);   // LPT
    const int sp   = blockIdx.x & 1;
    const int b    = blockIdx.y;
    const int lo   = sp * (qt + 1) / 2;
    const int hi   = (sp + 1) * (qt + 1) / 2;
    const int nu   = hi - lo;

    const int rowA = lane & 15;
    const int kofA = (lane & 16) >> 1;
    const int laneA = rowA * KSTR + kofA;
    const int rowB = (lane & 7) | ((lane & 16) >> 1);
    const int kofB = (lane & 8);
    const int laneB = rowB * KSTR + kofB;

    // start tile-0 fill immediately (overlaps Q staging below)
    if (nu > 0) { fill_tile(smb, b, lo, tid); CP_COMMIT(); }

    // ---- stage Q (fp16) through buf1's Kh area; capture fragments ----
    uint32_t qh[4][4];
    {
        char* qs = smc + BUF_B;
        const uint32_t qsb = smb + BUF_B;
        const char* qhp = (const char*)(g_qh + ((size_t)b * NT + (size_t)qt * 64) * NH);
#pragma unroll
        for (int u = 0; u < 4; u++) {
            int f = tid + u * 128;
            int r = f >> 3, c = f & 7;
            *(uint4*)(qs + (r * KSTR) * 2 + c * 16) = *(const uint4*)(qhp + r * 128 + c * 16);
        }
        __syncthreads();
#pragma unroll
        for (int kc = 0; kc < 4; kc++)
            ldsm4(qh[kc][0], qh[kc][1], qh[kc][2], qh[kc][3],
                  qsb + (uint32_t)(w * 16 * KSTR + kc * 16 + laneA) * 2);
        __syncthreads();
    }

    float o[8][4];
#pragma unroll
    for (int j = 0; j < 8; j++)
#pragma unroll
        for (int c = 0; c < 4; c++) o[j][c] = 0.f;
    float lth0 = 0.f, lth1 = 0.f;

    const int r0g = qt * 64 + w * 16 + g;
    const int r1g = r0g + 8;

    for (int u = 0; u < nu; u++) {
        const int kt = lo + u;
        const uint32_t bcur = smb + (u & 1) * BUF_B;
        const uint32_t kh_b = bcur;
        const uint32_t vt_b = bcur + TILE_B;

        CP_WAIT0();
        __syncthreads();
        if (u + 1 < nu) {
            fill_tile(smb + ((u + 1) & 1) * BUF_B, b, kt + 1, tid);
            CP_COMMIT();
        }

        // ---- per 16-key chunk: S -> exp -> PV (interleavable chains) ----
#pragma unroll
        for (int jp = 0; jp < 4; jp++) {
            // S chunk = Q * K^T for keys [16jp, 16jp+16)
            float s[2][4];
#pragma unroll
            for (int jj = 0; jj < 2; jj++)
#pragma unroll
                for (int c = 0; c < 4; c++) s[jj][c] = 0.f;

#pragma unroll
            for (int kc = 0; kc < 4; kc++) {
                uint32_t off = (uint32_t)(jp * 16 * KSTR + kc * 16 + laneB) * 2;
                uint32_t b0, b1, b2, b3;
                ldsm4(b0, b1, b2, b3, kh_b + off);
                mma16816(s[0][0], s[0][1], s[0][2], s[0][3],
                         qh[kc][0], qh[kc][1], qh[kc][2], qh[kc][3], b0, b1);
                mma16816(s[1][0], s[1][1], s[1][2], s[1][3],
                         qh[kc][0], qh[kc][1], qh[kc][2], qh[kc][3], b2, b3);
            }

            // exp + causal mask; pack rounded P; l from ROUNDED p
            uint32_t pa[2][2];
#pragma unroll
            for (int jj = 0; jj < 2; jj++) {
                int cb = kt * 64 + 8 * (2 * jp + jj) + 2 * l4;
                float p00 = (cb     <= r0g) ? __expf(s[jj][0]) : 0.f;
                float p01 = (cb + 1 <= r0g) ? __expf(s[jj][1]) : 0.f;
                float p10 = (cb     <= r1g) ? __expf(s[jj][2]) : 0.f;
                float p11 = (cb + 1 <= r1g) ? __expf(s[jj][3]) : 0.f;
                uint32_t h0 = cvt_h2(p00, p01);
                uint32_t h1 = cvt_h2(p10, p11);
                pa[jj][0] = h0;
                pa[jj][1] = h1;
                __half2 hh0 = *reinterpret_cast<__half2*>(&h0);
                __half2 hh1 = *reinterpret_cast<__half2*>(&h1);
                float2 f0 = __half22float2(hh0);
                float2 f1 = __half22float2(hh1);
                lth0 += f0.x + f0.y;
                lth1 += f1.x + f1.y;
            }

            // PV chunk: O += P[:, chunk] * V[chunk, :]
#pragma unroll
            for (int np = 0; np < 4; np++) {
                uint32_t off = (uint32_t)(np * 16 * KSTR + jp * 16 + laneB) * 2;
                uint32_t b0, b1, b2, b3;
                ldsm4(b0, b1, b2, b3, vt_b + off);
                mma16816(o[2*np][0], o[2*np][1], o[2*np][2], o[2*np][3],
                         pa[0][0], pa[0][1], pa[1][0], pa[1][1], b0, b1);
                mma16816(o[2*np+1][0], o[2*np+1][1], o[2*np+1][2], o[2*np+1][3],
                         pa[0][0], pa[0][1], pa[1][0], pa[1][1], b2, b3);
            }
        }
    }

    // ---- reduce l; store unnormalized partials ----
    lth0 += __shfl_xor_sync(0xffffffffu, lth0, 1);
    lth0 += __shfl_xor_sync(0xffffffffu, lth0, 2);
    lth1 += __shfl_xor_sync(0xffffffffu, lth1, 1);
    lth1 += __shfl_xor_sync(0xffffffffu, lth1, 2);

    const size_t row0 = (size_t)b * NT + r0g;
    const size_t row1 = (size_t)b * NT + r1g;
    float* p0 = g_po[sp] + row0 * NH;
    float* p1 = g_po[sp] + row1 * NH;
#pragma unroll
    for (int j = 0; j < 8; j++) {
        int col = 8 * j + 2 * l4;
        *(float2*)&p0[col] = make_float2(o[j][0], o[j][1]);
        *(float2*)&p1[col] = make_float2(o[j][2], o[j][3]);
    }
    if (l4 == 0) {
        g_pl[sp][row0] = lth0;
        g_pl[sp][row1] = lth1;
    }
}

// ---------------------------------------------------------------------------
// Kernel 3: combine the 2 split partials.  out = (o0+o1)/(l0+l1).
// ---------------------------------------------------------------------------
__global__ __launch_bounds__(256) void combine_kernel(float* __restrict__ out)
{
    size_t i = (size_t)blockIdx.x * 256 + threadIdx.x;
    size_t e = i * 4;
    size_t row = e >> 6;
    float inv = 1.0f / (g_pl[0][row] + g_pl[1][row]);
    float4 a = *(const float4*)&g_po[0][e];
    float4 c = *(const float4*)&g_po[1][e];
    float4 o = make_float4((a.x + c.x) * inv, (a.y + c.y) * inv,
                           (a.z + c.z) * inv, (a.w + c.w) * inv);
    *(float4*)&out[e] = o;
}

// ---------------------------------------------------------------------------
extern "C" void kernel_launch(void* const* d_in, const int* in_sizes, int n_in,
                              void* d_out, int out_size)
{
    const float* x  = (const float*)d_in[0];
    const float* Wk = (const float*)d_in[1];
    const float* Wq = (const float*)d_in[2];
    const float* Wv = (const float*)d_in[3];
    float* out = (float*)d_out;

    cudaFuncSetAttribute(attn_kernel,
                         cudaFuncAttributeMaxDynamicSharedMemorySize, SMEM_B);

    wt_prep_kernel<<<dim3(8, 3), 256>>>(Wk, Wq, Wv);
    proj_kernel<<<dim3(128, 2), 256>>>(x);
    attn_kernel<<<dim3(128, NB), 128, SMEM_B>>>();
    combine_kernel<<<1024, 256>>>(out);
}